// round 17
// baseline (speedup 1.0000x reference)
#include <cuda_runtime.h>
#include <cuda_fp16.h>
#include <cstdint>

#define N_NODES 100000
#define N_EDGES 3200000
#define D 128
#define SCAN_B 1024
#define N_SBLK ((N_NODES + SCAN_B - 1) / SCAN_B)   // 98

// ---------------- static device scratch (no allocation allowed) ----------------
__device__ __half         g_Y[(size_t)N_NODES * D];   // F @ W^T fp16 (25.6 MB)
__device__ unsigned       g_edge[N_EDGES];            // src<<15 | norm_q15
__device__ unsigned short g_rank[N_EDGES];            // within-node rank (6.4 MB)
__device__ int            g_cnt[N_NODES];             // histogram
__device__ int            g_off[N_NODES + 1];         // CSR offsets

// ---------------- host-side stream/event resources (created pre-main) ----------
struct HostRes {
    cudaStream_t s;
    cudaEvent_t  fork_ev, join_ev;
    void* cnt_addr = nullptr;
    HostRes() {
        cudaStreamCreateWithFlags(&s, cudaStreamNonBlocking);
        cudaEventCreateWithFlags(&fork_ev, cudaEventDisableTiming);
        cudaEventCreateWithFlags(&join_ev, cudaEventDisableTiming);
    }
};
static HostRes g_res;

// ---------------------------------------------------------------------------
// histogram of dst, 8 edges per thread (2x int4 loads, 8 atomics in flight),
// capturing each edge's within-node rank as u16
// ---------------------------------------------------------------------------
__global__ __launch_bounds__(256) void hist_kernel(const int* __restrict__ dst) {
    int i = (blockIdx.x * blockDim.x + threadIdx.x) * 8;   // N_EDGES % 8 == 0
    if (i < N_EDGES) {
        int4 a = *(const int4*)(dst + i);
        int4 b = *(const int4*)(dst + i + 4);
        unsigned short r[8];
        r[0] = (unsigned short)atomicAdd(&g_cnt[a.x], 1);
        r[1] = (unsigned short)atomicAdd(&g_cnt[a.y], 1);
        r[2] = (unsigned short)atomicAdd(&g_cnt[a.z], 1);
        r[3] = (unsigned short)atomicAdd(&g_cnt[a.w], 1);
        r[4] = (unsigned short)atomicAdd(&g_cnt[b.x], 1);
        r[5] = (unsigned short)atomicAdd(&g_cnt[b.y], 1);
        r[6] = (unsigned short)atomicAdd(&g_cnt[b.z], 1);
        r[7] = (unsigned short)atomicAdd(&g_cnt[b.w], 1);
        *(uint4*)(g_rank + i) = *(uint4*)r;   // 16B aligned (i % 8 == 0)
    }
}

// ---------------------------------------------------------------------------
// single-kernel scan: each block sums its preceding g_cnt range (block
// prefix), then local Hillis-Steele scan -> g_off
// ---------------------------------------------------------------------------
__global__ __launch_bounds__(SCAN_B) void offsets_kernel() {
    __shared__ int sh[SCAN_B];
    __shared__ int red[32];
    __shared__ int s_bpref;

    int tid = threadIdx.x;
    int start = blockIdx.x * SCAN_B;

    int pre = 0;
    for (int i = tid; i < start; i += SCAN_B) pre += g_cnt[i];
#pragma unroll
    for (int o = 16; o > 0; o >>= 1) pre += __shfl_xor_sync(0xffffffffu, pre, o);
    if ((tid & 31) == 0) red[tid >> 5] = pre;
    __syncthreads();
    if (tid < 32) {
        int w = (tid < SCAN_B / 32) ? red[tid] : 0;
#pragma unroll
        for (int o = 16; o > 0; o >>= 1) w += __shfl_xor_sync(0xffffffffu, w, o);
        if (tid == 0) s_bpref = w;
    }

    int idx = start + tid;
    int v = (idx < N_NODES) ? g_cnt[idx] : 0;
    sh[tid] = v;
    __syncthreads();
    for (int o = 1; o < SCAN_B; o <<= 1) {
        int t = (tid >= o) ? sh[tid - o] : 0;
        __syncthreads();
        sh[tid] += t;
        __syncthreads();
    }
    if (idx < N_NODES)
        g_off[idx] = s_bpref + sh[tid] - v;
    if (idx == 0) g_off[N_NODES] = N_EDGES;
}

// ---------------------------------------------------------------------------
// fill CSR edge list WITHOUT atomics, 8 edges per thread (8x MLP):
// pos = off[dst] + rank; packed word: (src << 15) | floor(norm * 32768)
// ---------------------------------------------------------------------------
__global__ __launch_bounds__(256) void fill_kernel(const int* __restrict__ src,
                                                   const int* __restrict__ dst,
                                                   const float* __restrict__ norm) {
    int i = (blockIdx.x * blockDim.x + threadIdx.x) * 8;
    if (i < N_EDGES) {
        int4   da = *(const int4*)(dst + i);
        int4   db = *(const int4*)(dst + i + 4);
        int4   sa = *(const int4*)(src + i);
        int4   sb = *(const int4*)(src + i + 4);
        float4 na = *(const float4*)(norm + i);
        float4 nb = *(const float4*)(norm + i + 4);
        uint4  rr = *(const uint4*)(g_rank + i);
        const unsigned short* r = (const unsigned short*)&rr;

        int d[8] = {da.x, da.y, da.z, da.w, db.x, db.y, db.z, db.w};
        int s[8] = {sa.x, sa.y, sa.z, sa.w, sb.x, sb.y, sb.z, sb.w};
        float nv[8] = {na.x, na.y, na.z, na.w, nb.x, nb.y, nb.z, nb.w};

        int o[8];
#pragma unroll
        for (int j = 0; j < 8; j++) o[j] = __ldg(&g_off[d[j]]);

#pragma unroll
        for (int j = 0; j < 8; j++) {
            unsigned q = (unsigned)(nv[j] * 32768.0f);
            if (q > 32767u) q = 32767u;
            g_edge[o[j] + r[j]] = ((unsigned)s[j] << 15) | q;
        }
    }
}

// ---------------------------------------------------------------------------
// Y = F @ W^T via tensor cores: mma.sync m16n8k16 fp16 inputs, fp32 accum.
// ---------------------------------------------------------------------------
__device__ __forceinline__ uint32_t pack_h2(float2 f) {
    __half2 h = __floats2half2_rn(f.x, f.y);
    return *(uint32_t*)&h;
}

__global__ __launch_bounds__(256) void gemm_kernel(const float* __restrict__ F,
                                                   const float* __restrict__ W) {
    __shared__ __half Wsm[128][136];

    int tid = threadIdx.x;
    for (int idx = tid; idx < 128 * 32; idx += 256) {
        int n  = idx >> 5;
        int c4 = idx & 31;
        float4 w4 = ((const float4*)W)[n * 32 + c4];
        *(__half2*)&Wsm[n][c4 * 4]     = __floats2half2_rn(w4.x, w4.y);
        *(__half2*)&Wsm[n][c4 * 4 + 2] = __floats2half2_rn(w4.z, w4.w);
    }
    __syncthreads();

    int wid  = tid >> 5;
    int lane = tid & 31;
    int g    = lane >> 2;
    int tg   = lane & 3;

    int rowA = blockIdx.x * 128 + wid * 16 + g;
    bool ok0 = rowA < N_NODES;
    bool ok1 = (rowA + 8) < N_NODES;
    const float* Fr0 = F + (size_t)rowA * D;
    const float* Fr1 = Fr0 + (size_t)8 * D;

    float acc[16][4];
#pragma unroll
    for (int j = 0; j < 16; j++)
#pragma unroll
        for (int c = 0; c < 4; c++) acc[j][c] = 0.0f;

#pragma unroll
    for (int ks = 0; ks < 8; ks++) {
        int kb = ks * 16;
        float2 z = make_float2(0.f, 0.f);
        float2 f00 = ok0 ? *(const float2*)(Fr0 + kb + 2 * tg)     : z;
        float2 f10 = ok1 ? *(const float2*)(Fr1 + kb + 2 * tg)     : z;
        float2 f01 = ok0 ? *(const float2*)(Fr0 + kb + 2 * tg + 8) : z;
        float2 f11 = ok1 ? *(const float2*)(Fr1 + kb + 2 * tg + 8) : z;
        uint32_t a0 = pack_h2(f00);
        uint32_t a1 = pack_h2(f10);
        uint32_t a2 = pack_h2(f01);
        uint32_t a3 = pack_h2(f11);

#pragma unroll
        for (int j = 0; j < 16; j++) {
            int n = j * 8 + g;
            uint32_t b0 = *(const uint32_t*)&Wsm[n][kb + 2 * tg];
            uint32_t b1 = *(const uint32_t*)&Wsm[n][kb + 2 * tg + 8];
            asm volatile(
                "mma.sync.aligned.m16n8k16.row.col.f32.f16.f16.f32 "
                "{%0,%1,%2,%3}, {%4,%5,%6,%7}, {%8,%9}, {%0,%1,%2,%3};"
                : "+f"(acc[j][0]), "+f"(acc[j][1]), "+f"(acc[j][2]), "+f"(acc[j][3])
                : "r"(a0), "r"(a1), "r"(a2), "r"(a3), "r"(b0), "r"(b1));
        }
    }

#pragma unroll
    for (int j = 0; j < 16; j++) {
        int n = j * 8 + 2 * tg;
        if (ok0)
            *(__half2*)(g_Y + (size_t)rowA * D + n) =
                __floats2half2_rn(acc[j][0], acc[j][1]);
        if (ok1)
            *(__half2*)(g_Y + (size_t)(rowA + 8) * D + n) =
                __floats2half2_rn(acc[j][2], acc[j][3]);
    }
}

// ---------------------------------------------------------------------------
// per-node reduction (proven form): one warp/node, half-warp covers a 256B
// Y row, lane owns 8 halfs (LDG.128); 4 edge words + 4 gathers batched;
// .cs on edges/out to keep Y in L2.
// ---------------------------------------------------------------------------
__device__ __forceinline__ void fma8(float acc[8], uint4 u, float n) {
    float2 f0 = __half22float2(*(__half2*)&u.x);
    float2 f1 = __half22float2(*(__half2*)&u.y);
    float2 f2 = __half22float2(*(__half2*)&u.z);
    float2 f3 = __half22float2(*(__half2*)&u.w);
    acc[0] = fmaf(n, f0.x, acc[0]); acc[1] = fmaf(n, f0.y, acc[1]);
    acc[2] = fmaf(n, f1.x, acc[2]); acc[3] = fmaf(n, f1.y, acc[3]);
    acc[4] = fmaf(n, f2.x, acc[4]); acc[5] = fmaf(n, f2.y, acc[5]);
    acc[6] = fmaf(n, f3.x, acc[6]); acc[7] = fmaf(n, f3.y, acc[7]);
}

__device__ __forceinline__ void edge_fma(float acc[8], const __half* Ycol, unsigned w) {
    unsigned s = w >> 15;
    float   n = (float)(w & 0x7FFFu) * (1.0f / 32768.0f);
    uint4   u = *(const uint4*)(Ycol + (size_t)s * D);
    fma8(acc, u, n);
}

__global__ __launch_bounds__(256) void reduce_kernel(float* __restrict__ out,
                                                     const float* __restrict__ bias) {
    int warp = (blockIdx.x * blockDim.x + threadIdx.x) >> 5;
    int lane = threadIdx.x & 31;
    if (warp >= N_NODES) return;

    int beg = __ldg(&g_off[warp]);
    int end = __ldg(&g_off[warp + 1]);

    int half = lane >> 4;
    int hl   = lane & 15;

    float acc[8] = {0.f, 0.f, 0.f, 0.f, 0.f, 0.f, 0.f, 0.f};
    const __half* Ycol = g_Y + hl * 8;

    int e = beg + half;
    for (; e + 6 < end; e += 8) {
        unsigned w0 = __ldcs(&g_edge[e]);
        unsigned w1 = __ldcs(&g_edge[e + 2]);
        unsigned w2 = __ldcs(&g_edge[e + 4]);
        unsigned w3 = __ldcs(&g_edge[e + 6]);
        unsigned s0 = w0 >> 15, s1 = w1 >> 15, s2 = w2 >> 15, s3 = w3 >> 15;
        uint4 u0 = *(const uint4*)(Ycol + (size_t)s0 * D);
        uint4 u1 = *(const uint4*)(Ycol + (size_t)s1 * D);
        uint4 u2 = *(const uint4*)(Ycol + (size_t)s2 * D);
        uint4 u3 = *(const uint4*)(Ycol + (size_t)s3 * D);
        fma8(acc, u0, (float)(w0 & 0x7FFFu) * (1.0f / 32768.0f));
        fma8(acc, u1, (float)(w1 & 0x7FFFu) * (1.0f / 32768.0f));
        fma8(acc, u2, (float)(w2 & 0x7FFFu) * (1.0f / 32768.0f));
        fma8(acc, u3, (float)(w3 & 0x7FFFu) * (1.0f / 32768.0f));
    }
    for (; e < end; e += 2)
        edge_fma(acc, Ycol, __ldcs(&g_edge[e]));

#pragma unroll
    for (int j = 0; j < 8; j++)
        acc[j] += __shfl_xor_sync(0xffffffffu, acc[j], 16);

    if (half == 0) {
        const float4* b4 = (const float4*)bias;
        float4 b0 = b4[hl * 2], b1 = b4[hl * 2 + 1];
        float4* o = (float4*)(out + (size_t)warp * D + hl * 8);
        __stcs(o,     make_float4(acc[0] + b0.x, acc[1] + b0.y,
                                  acc[2] + b0.z, acc[3] + b0.w));
        __stcs(o + 1, make_float4(acc[4] + b1.x, acc[5] + b1.y,
                                  acc[6] + b1.z, acc[7] + b1.w));
    }
}

// ---------------------------------------------------------------------------
extern "C" void kernel_launch(void* const* d_in, const int* in_sizes, int n_in,
                              void* d_out, int out_size) {
    const float* features = (const float*)d_in[0];
    const float* norm     = (const float*)d_in[1];
    const int*   src      = (const int*)d_in[2];
    const int*   dst      = (const int*)d_in[3];
    const float* weight   = (const float*)d_in[4];
    const float* bias     = (const float*)d_in[5];
    float*       out      = (float*)d_out;

    if (!g_res.cnt_addr) cudaGetSymbolAddress(&g_res.cnt_addr, g_cnt);

    // Fork: tensor-core GEMM on side stream, concurrent with the sort pipeline.
    cudaEventRecord(g_res.fork_ev, 0);
    cudaStreamWaitEvent(g_res.s, g_res.fork_ev, 0);
    gemm_kernel<<<(N_NODES + 127) / 128, 256, 0, g_res.s>>>(features, weight);
    cudaEventRecord(g_res.join_ev, g_res.s);

    // Main stream: counting sort by dst (rank captured in hist; 1-kernel scan)
    cudaMemsetAsync(g_res.cnt_addr, 0, N_NODES * sizeof(int), 0);
    hist_kernel<<<(N_EDGES / 8 + 255) / 256, 256>>>(dst);
    offsets_kernel<<<N_SBLK, SCAN_B>>>();
    fill_kernel<<<(N_EDGES / 8 + 255) / 256, 256>>>(src, dst, norm);

    // Join, then reduce (one warp per node)
    cudaStreamWaitEvent(0, g_res.join_ev, 0);
    long long total_threads = (long long)N_NODES * 32;
    reduce_kernel<<<(int)((total_threads + 255) / 256), 256>>>(out, bias);
}